// round 17
// baseline (speedup 1.0000x reference)
#include <cuda_runtime.h>
#include <cuda_fp16.h>
#include <cstdint>

#define E_ 8
#define D_ 1024
#define H_ 4096
#define O_ 1024
#define B_ 4096
#define MAXROWS 9216          // 8192 rows + per-expert padding to 128, <= 72 tiles
#define NTILES  72            // MAXROWS / 128

// GEMM smem layout (uint32 indices): As[3][128][20] | Bs[3][128][20] | tok[128] | wgt[128]
#define STG_U32   2560        // 128*20
#define BS_OFF    7680        // 3*2560
#define TOK_OFF   15360
#define WGT_OFF   15488
#define GEMM_SMEM_BYTES (15616 * 4)   // 62464

// ---------------- static device scratch (no allocations allowed) ----------------
__device__ __half g_h  [(size_t)MAXROWS * H_];   // gelu(x@W1+b1), half
__device__ __half g_xa [(size_t)MAXROWS * D_];   // gathered x rows, half
__device__ __half g_w1t[(size_t)E_ * H_ * D_];   // w1^T [e][h][d] half
__device__ __half g_w2t[(size_t)E_ * O_ * H_];   // w2^T [e][o][h] half
__device__ int    g_tok[MAXROWS];
__device__ float  g_wgt[MAXROWS];
__device__ int    g_counts[E_];                  // zero at start of every run (re-zeroed by setup)
__device__ int    g_cnt_saved[E_];
__device__ int    g_tile_expert[NTILES];
__device__ float  g_probs[(size_t)B_ * E_];
__device__ int    g_topk[B_ * 2];
__device__ float  g_topw[B_ * 2];

// ---------------- helpers ----------------
__device__ __forceinline__ void cp16(void* s, const void* g) {
    uint32_t sa = (uint32_t)__cvta_generic_to_shared(s);
    asm volatile("cp.async.cg.shared.global [%0], [%1], 16;\n" :: "r"(sa), "l"(g));
}
#define CP_COMMIT() asm volatile("cp.async.commit_group;\n")

__device__ __forceinline__ uint32_t smem_u32(const void* p) {
    return (uint32_t)__cvta_generic_to_shared(p);
}

// ---------------- router: 1 warp per token; also zeroes its slice of out ---------
__global__ __launch_bounds__(256) void router_kernel(
    const float* __restrict__ x, const float* __restrict__ gw, const float* __restrict__ gb,
    float* __restrict__ out)
{
    {
        float4* o4 = (float4*)(out + (size_t)blockIdx.x * 8 * O_);
        #pragma unroll
        for (int i = 0; i < 8; ++i)
            o4[threadIdx.x + i * 256] = make_float4(0.f, 0.f, 0.f, 0.f);
    }

    __shared__ float4 sgw[E_ * D_ / 4];    // 32 KB gate matrix
    int tid = threadIdx.x;
    for (int i = tid; i < E_ * D_ / 4; i += 256) sgw[i] = ((const float4*)gw)[i];
    __syncthreads();

    int warp = tid >> 5, lane = tid & 31;
    int t = blockIdx.x * 8 + warp;
    const float4* xr = (const float4*)(x + (size_t)t * D_);

    float acc[E_];
    #pragma unroll
    for (int e = 0; e < E_; ++e) acc[e] = 0.f;

    #pragma unroll
    for (int i = 0; i < D_ / 128; ++i) {
        float4 xv = xr[lane + 32 * i];
        #pragma unroll
        for (int e = 0; e < E_; ++e) {
            float4 g = sgw[e * (D_ / 4) + lane + 32 * i];
            acc[e] += xv.x * g.x + xv.y * g.y + xv.z * g.z + xv.w * g.w;
        }
    }
    #pragma unroll
    for (int e = 0; e < E_; ++e)
        #pragma unroll
        for (int o = 16; o; o >>= 1) acc[e] += __shfl_down_sync(0xffffffffu, acc[e], o);

    if (lane == 0) {
        float l[E_], m = -1e30f;
        #pragma unroll
        for (int e = 0; e < E_; ++e) { l[e] = acc[e] + gb[e]; m = fmaxf(m, l[e]); }
        float p[E_], s = 0.f;
        #pragma unroll
        for (int e = 0; e < E_; ++e) { p[e] = expf(l[e] - m); s += p[e]; }
        float inv = 1.f / s;
        int i0 = 0; float m0 = -1.f;
        #pragma unroll
        for (int e = 0; e < E_; ++e) {
            p[e] *= inv;
            g_probs[(size_t)t * E_ + e] = p[e];
            if (p[e] > m0) { m0 = p[e]; i0 = e; }
        }
        int i1 = -1; float m1 = -1.f;
        #pragma unroll
        for (int e = 0; e < E_; ++e)
            if (e != i0 && p[e] > m1) { m1 = p[e]; i1 = e; }
        float inv2 = 1.f / (m0 + m1 + 1e-9f);
        g_topk[t * 2 + 0] = i0;  g_topw[t * 2 + 0] = m0 * inv2;
        g_topk[t * 2 + 1] = i1;  g_topw[t * 2 + 1] = m1 * inv2;
        atomicAdd(&g_counts[i0], 1);
        atomicAdd(&g_counts[i1], 1);
    }
}

// ---------------- setup: offsets, tile map, scatter, pads; resets g_counts ------
__global__ void setup_kernel() {
    __shared__ int offs[E_], cnt[E_], padc[E_], cur[E_];
    int tid = threadIdx.x;
    if (tid == 0) {
        int acc = 0;
        for (int e = 0; e < E_; ++e) {
            cnt[e] = g_counts[e];
            offs[e] = acc;
            padc[e] = ((cnt[e] + 127) >> 7) << 7;
            acc += padc[e];
        }
        int tt = 0;
        for (int e = 0; e < E_; ++e)
            for (int j = 0; j < (padc[e] >> 7); ++j) g_tile_expert[tt++] = e;
        for (; tt < NTILES; ++tt) g_tile_expert[tt] = -1;
    }
    if (tid < E_) cur[tid] = 0;
    __syncthreads();

    if (tid < E_) {
        g_cnt_saved[tid] = cnt[tid];
        g_counts[tid] = 0;
    }

    for (int idx = tid; idx < B_ * 2; idx += blockDim.x) {
        int t = idx >> 1;
        int e = g_topk[idx];
        int pos = offs[e] + atomicAdd(&cur[e], 1);
        g_tok[pos] = t;
        g_wgt[pos] = g_topw[idx];
    }
    for (int e = 0; e < E_; ++e)
        for (int j = cnt[e] + tid; j < padc[e]; j += blockDim.x) {
            g_tok[offs[e] + j] = 0;
            g_wgt[offs[e] + j] = 0.f;
        }
}

// ---------------- generic 32x32 transpose tile helper (f32 in -> half out) ------
template<int KD, int ND>
__device__ __forceinline__ void transpose_tile(
    const float* __restrict__ ine, __half* __restrict__ oute_h, int n0, int k0)
{
    __shared__ float sm[32][33];
    int tx = threadIdx.x & 31, ty = threadIdx.x >> 5;
    #pragma unroll
    for (int i = 0; i < 4; ++i)
        sm[ty + i * 8][tx] = ine[(size_t)(k0 + ty + i * 8) * ND + n0 + tx];
    __syncthreads();
    __half2* oute = (__half2*)oute_h;
    int wk2 = threadIdx.x & 15;
    int wn  = threadIdx.x >> 4;
    #pragma unroll
    for (int i = 0; i < 2; ++i) {
        int n = wn + i * 16;
        oute[(size_t)(n0 + n) * (KD / 2) + (k0 >> 1) + wk2] =
            __floats2half2_rn(sm[wk2 * 2][n], sm[wk2 * 2 + 1][n]);
    }
}

// ---------------- prep1: gather(x->g_xa) + w1^T -> g_w1t + w2^T -> g_w2t --------
// blocks [0,576): gather; [576, 576+32768): w1T; [576+32768, 576+65536): w2T
#define GATHER_BLOCKS 576
#define W1T_BLOCKS (E_ * (D_ / 32) * (H_ / 32))   // 32768
#define W2T_BLOCKS (E_ * (H_ / 32) * (O_ / 32))   // 32768
__global__ __launch_bounds__(256) void prep1_kernel(
    const float* __restrict__ x, const float* __restrict__ w1, const float* __restrict__ w2)
{
    int id = blockIdx.x;
    if (id < GATHER_BLOCKS) {
        int tile = id >> 3;
        if (g_tile_expert[tile] < 0) return;
        int r0 = tile * 128 + (id & 7) * 16;
        for (int r = r0; r < r0 + 16; ++r) {
            const float4* src = (const float4*)(x + (size_t)g_tok[r] * D_);
            __half2* dst = (__half2*)(g_xa + (size_t)r * D_);
            int j = threadIdx.x;
            float4 v = src[j];
            dst[j * 2 + 0] = __floats2half2_rn(v.x, v.y);
            dst[j * 2 + 1] = __floats2half2_rn(v.z, v.w);
        }
    } else if (id < GATHER_BLOCKS + W1T_BLOCKS) {
        int id2 = id - GATHER_BLOCKS;                 // [0, 8*32*128)
        int e = id2 >> 12;
        int rem = id2 & 4095;
        int n0 = (rem & 127) * 32;                    // along H_ (ND=H_, 128 tiles)
        int k0 = (rem >> 7) * 32;                     // along D_ (32 tiles)
        transpose_tile<D_, H_>(w1 + (size_t)e * D_ * H_,
                               g_w1t + (size_t)e * H_ * D_, n0, k0);
    } else {
        int id3 = id - GATHER_BLOCKS - W1T_BLOCKS;    // [0, 8*128*32)
        int e = id3 >> 12;
        int rem = id3 & 4095;
        int n0 = (rem & 31) * 32;                     // along O_ (ND=O_, 32 tiles)
        int k0 = (rem >> 5) * 32;                     // along H_ (128 tiles)
        transpose_tile<H_, O_>(w2 + (size_t)e * H_ * O_,
                               g_w2t + (size_t)e * O_ * H_, n0, k0);
    }
}

// ---------------- grouped FP16 GEMM: 3-stage ring, hoisted fragment loads -------
// Inner loop issues ALL 12 ldmatrix (both kk halves) before the 32 MMAs so the
// load latencies overlap each other instead of serializing with MMA bursts.
template<int KDIM, int NTOT, bool FIRST>
__global__ __launch_bounds__(256, 2) void moe_gemm_h(
    const __half* __restrict__ A,
    const __half* __restrict__ W,
    const float* __restrict__ bias,
    float* __restrict__ out)
{
    int e = g_tile_expert[blockIdx.y];
    if (e < 0) return;
    const int row0 = blockIdx.y * 128;
    const int n0   = blockIdx.x * 128;
    const int tid  = threadIdx.x;

    extern __shared__ uint32_t dsm[];
    uint32_t (*As)[128][20] = (uint32_t(*)[128][20])dsm;
    uint32_t (*Bs)[128][20] = (uint32_t(*)[128][20])(dsm + BS_OFF);
    int*   s_tok = (int*)(dsm + TOK_OFF);
    float* s_wgt = (float*)(dsm + WGT_OFF);

    if (!FIRST && tid < 128) { s_tok[tid] = g_tok[row0 + tid]; s_wgt[tid] = g_wgt[row0 + tid]; }

    const __half* We = W + (size_t)e * NTOT * KDIM;   // [n][k]

    auto load_tile = [&](int kt, int s) {
        const int kof = kt * 32;
        #pragma unroll
        for (int j = 0; j < 4; ++j) {
            int id = tid + j * 256;
            if (id < 512) {                         // A: 128 rows x 4 chunks(16B)
                int r = id >> 2, g = id & 3;
                cp16(&As[s][r][g * 4], A + (size_t)(row0 + r) * KDIM + kof + g * 8);
            } else {                                // B: 128 n-rows x 4 chunks
                int id2 = id - 512;
                int r = id2 >> 2, g = id2 & 3;
                cp16(&Bs[s][r][g * 4], We + (size_t)(n0 + r) * KDIM + kof + g * 8);
            }
        }
    };

    const int warp = tid >> 5, lane = tid & 31;
    const int wm = (warp & 3) * 32;
    const int wn = (warp >> 2) * 64;
    const int gid = lane >> 2, tig = lane & 3;

    const int lrow = lane & 15, lhi = lane >> 4;
    const uint32_t as_s = smem_u32(&As[0][0][0]);
    const uint32_t a_lane = as_s + (uint32_t)(wm + lrow) * 80u + (uint32_t)lhi * 16u;

    const uint32_t bs_s = smem_u32(&Bs[0][0][0]);
    const uint32_t b_lane = bs_s
        + (uint32_t)(wn + (lane & 7) + ((lane >> 4) & 1) * 8) * 80u
        + (uint32_t)((lane >> 3) & 1) * 16u;

    float acc[2][8][4];
    #pragma unroll
    for (int mf = 0; mf < 2; ++mf)
        #pragma unroll
        for (int nf = 0; nf < 8; ++nf)
            #pragma unroll
            for (int i = 0; i < 4; ++i) acc[mf][nf][i] = 0.f;

    constexpr int KT = KDIM / 32;
    load_tile(0, 0); CP_COMMIT();
    load_tile(1, 1); CP_COMMIT();

    int s = 0;
    for (int kt = 0; kt < KT; ++kt) {
        if (kt + 1 < KT) asm volatile("cp.async.wait_group 1;\n");
        else             asm volatile("cp.async.wait_group 0;\n");
        __syncthreads();   // all warps done reading stage (kt+2)%3 (= iter kt-1's stage)

        if (kt + 2 < KT) { load_tile(kt + 2, (kt + 2) % 3); CP_COMMIT(); }

        const uint32_t soff = (uint32_t)s * 10240u;

        // ---- hoisted fragment loads: both kk halves, 12 ldmatrix back-to-back ----
        uint32_t a[2][2][4], b[2][8][2];
        #pragma unroll
        for (int h = 0; h < 2; ++h) {
            const uint32_t kb = (uint32_t)h * 32u;      // kk*2 bytes, kk = h*16
            #pragma unroll
            for (int mf = 0; mf < 2; ++mf) {
                uint32_t addr = a_lane + soff + (uint32_t)mf * 1280u + kb;
                asm volatile(
                    "ldmatrix.sync.aligned.m8n8.x4.shared.b16 {%0,%1,%2,%3}, [%4];"
                    : "=r"(a[h][mf][0]), "=r"(a[h][mf][1]), "=r"(a[h][mf][2]), "=r"(a[h][mf][3])
                    : "r"(addr));
            }
            #pragma unroll
            for (int nf = 0; nf < 8; nf += 2) {
                uint32_t addr = b_lane + soff + (uint32_t)nf * 640u + kb;
                asm volatile(
                    "ldmatrix.sync.aligned.m8n8.x4.shared.b16 {%0,%1,%2,%3}, [%4];"
                    : "=r"(b[h][nf][0]), "=r"(b[h][nf][1]),
                      "=r"(b[h][nf + 1][0]), "=r"(b[h][nf + 1][1])
                    : "r"(addr));
            }
        }
        // ---- 32 MMAs, inputs all in flight/ready ----
        #pragma unroll
        for (int h = 0; h < 2; ++h)
            #pragma unroll
            for (int mf = 0; mf < 2; ++mf)
                #pragma unroll
                for (int nf = 0; nf < 8; ++nf)
                    asm volatile(
                        "mma.sync.aligned.m16n8k16.row.col.f32.f16.f16.f32 "
                        "{%0,%1,%2,%3},{%4,%5,%6,%7},{%8,%9},{%0,%1,%2,%3};\n"
                        : "+f"(acc[mf][nf][0]), "+f"(acc[mf][nf][1]),
                          "+f"(acc[mf][nf][2]), "+f"(acc[mf][nf][3])
                        : "r"(a[h][mf][0]), "r"(a[h][mf][1]), "r"(a[h][mf][2]), "r"(a[h][mf][3]),
                          "r"(b[h][nf][0]), "r"(b[h][nf][1]));
        s = (s + 1 == 3) ? 0 : s + 1;
    }

    #pragma unroll
    for (int mf = 0; mf < 2; ++mf) {
        int rl = wm + mf * 16 + gid;
        #pragma unroll
        for (int nf = 0; nf < 8; ++nf) {
            int gc = n0 + wn + nf * 8 + tig * 2;
            float v00 = acc[mf][nf][0] + bias[e * NTOT + gc];
            float v01 = acc[mf][nf][1] + bias[e * NTOT + gc + 1];
            float v10 = acc[mf][nf][2] + bias[e * NTOT + gc];
            float v11 = acc[mf][nf][3] + bias[e * NTOT + gc + 1];
            if constexpr (FIRST) {
                v00 = 0.5f * v00 * (1.f + erff(v00 * 0.70710678118654752f));
                v01 = 0.5f * v01 * (1.f + erff(v01 * 0.70710678118654752f));
                v10 = 0.5f * v10 * (1.f + erff(v10 * 0.70710678118654752f));
                v11 = 0.5f * v11 * (1.f + erff(v11 * 0.70710678118654752f));
                *(__half2*)&g_h[(size_t)(row0 + rl)     * H_ + gc] = __floats2half2_rn(v00, v01);
                *(__half2*)&g_h[(size_t)(row0 + rl + 8) * H_ + gc] = __floats2half2_rn(v10, v11);
            } else {
                float w0 = s_wgt[rl];     int t0 = s_tok[rl];
                float w8 = s_wgt[rl + 8]; int t8 = s_tok[rl + 8];
                atomicAdd(&out[(size_t)t0 * O_ + gc    ], w0 * v00);
                atomicAdd(&out[(size_t)t0 * O_ + gc + 1], w0 * v01);
                atomicAdd(&out[(size_t)t8 * O_ + gc    ], w8 * v10);
                atomicAdd(&out[(size_t)t8 * O_ + gc + 1], w8 * v11);
            }
        }
    }
}

// ---------------- aux loss: deterministic fixed-order reduction -----------------
__global__ void aux_kernel(float* __restrict__ out, int aux_idx) {
    __shared__ float sm[256 * E_];
    int tid = threadIdx.x;
    float ps[E_];
    #pragma unroll
    for (int e = 0; e < E_; ++e) ps[e] = 0.f;
    for (int t = tid; t < B_; t += 256)
        #pragma unroll
        for (int e = 0; e < E_; ++e) ps[e] += g_probs[(size_t)t * E_ + e];
    #pragma unroll
    for (int e = 0; e < E_; ++e) sm[tid * E_ + e] = ps[e];
    __syncthreads();
    for (int o = 128; o; o >>= 1) {
        if (tid < o)
            #pragma unroll
            for (int e = 0; e < E_; ++e) sm[tid * E_ + e] += sm[(tid + o) * E_ + e];
        __syncthreads();
    }
    if (tid == 0) {
        float aux = 0.f;
        #pragma unroll
        for (int e = 0; e < E_; ++e) {
            float f = (float)g_cnt_saved[e] * (1.f / B_);
            float p = sm[e] * (1.f / B_);
            aux += f * p;
        }
        out[aux_idx] = aux * (0.01f * E_);
    }
}

// ---------------- launch ----------------
extern "C" void kernel_launch(void* const* d_in, const int* in_sizes, int n_in,
                              void* d_out, int out_size)
{
    const float* x  = (const float*)d_in[0];
    const float* w1 = (const float*)d_in[1];
    const float* b1 = (const float*)d_in[2];
    const float* w2 = (const float*)d_in[3];
    const float* b2 = (const float*)d_in[4];
    const float* gw = (const float*)d_in[5];
    const float* gb = (const float*)d_in[6];
    float* out = (float*)d_out;

    __half* p_xa;  cudaGetSymbolAddress((void**)&p_xa,  g_xa);
    __half* p_h;   cudaGetSymbolAddress((void**)&p_h,   g_h);
    __half* p_w1t; cudaGetSymbolAddress((void**)&p_w1t, g_w1t);
    __half* p_w2t; cudaGetSymbolAddress((void**)&p_w2t, g_w2t);

    cudaFuncSetAttribute(moe_gemm_h<D_, H_, true >,
                         cudaFuncAttributeMaxDynamicSharedMemorySize, GEMM_SMEM_BYTES);
    cudaFuncSetAttribute(moe_gemm_h<H_, O_, false>,
                         cudaFuncAttributeMaxDynamicSharedMemorySize, GEMM_SMEM_BYTES);

    // 1: router (zeroes out); 2: setup; 3: prep (gather + both transposes)
    router_kernel<<<B_ / 8, 256>>>(x, gw, gb, out);
    setup_kernel<<<1, 256>>>();
    prep1_kernel<<<GATHER_BLOCKS + W1T_BLOCKS + W2T_BLOCKS, 256>>>(x, w1, w2);
    // 4: GEMM1 (ncu capture slot); 5: GEMM2; 6: aux
    moe_gemm_h<D_, H_, true ><<<dim3(H_ / 128, NTILES), 256, GEMM_SMEM_BYTES>>>(p_xa, p_w1t, b1, out);
    moe_gemm_h<H_, O_, false><<<dim3(O_ / 128, NTILES), 256, GEMM_SMEM_BYTES>>>(p_h, p_w2t, b2, out);
    aux_kernel<<<1, 256>>>(out, out_size - 1);
}